// round 3
// baseline (speedup 1.0000x reference)
#include <cuda_runtime.h>
#include <cstdint>

// out: [16384, 2046] f32 = tanh(row) broadcast over batch rows.
// Row depends only on kernel_weights[6]; `values` input is shape-only.
//
// Two consecutive rows = 4092 floats = 16368 bytes (16B-multiple), and the
// pattern repeats with that period across the whole 134MB output. So:
//  (1) compute the 4092-float tile once,
//  (2) blast it out 8192 times with TMA bulk stores (smem -> global).

#define BS          16384
#define L_OUT       2046
#define TILE_FLOATS 4092                 // 2 rows
#define TILE_BYTES  (TILE_FLOATS * 4)    // 16368, multiple of 16
#define TILE_F4     1023
#define GROUPS      (BS / 2)             // 8192
#define NBLOCKS     1024
#define G_PER_B     (GROUPS / NBLOCKS)   // 8 bulk stores per block
#define TPB         128

#define NEG_LOG_NORM 1.3836465597893728f   // -log(0.1*sqrt(2*pi))
#define INV_STD      10.0f

__device__ __align__(16) float g_tile[TILE_FLOATS];

__device__ __forceinline__ float row_value(int c, const float* __restrict__ w) {
    const float means[6] = {0.0f, 0.2f, 0.4f, 0.6f, 0.8f, 1.0f};
    float pos = (float)c / (float)L_OUT;
    float acc = 0.0f;
#pragma unroll
    for (int k = 0; k < 6; k++) {
        float z = (pos - means[k]) * INV_STD;
        float pdf = expf(fmaf(-0.5f * z, z, NEG_LOG_NORM));
        acc = fmaf(w[k], pdf, acc);
    }
    return tanhf(acc);
}

__global__ void compute_tile_kernel(const float* __restrict__ kw) {
    int c = blockIdx.x * blockDim.x + threadIdx.x;
    if (c >= TILE_FLOATS) return;
    float w[6];
#pragma unroll
    for (int k = 0; k < 6; k++) w[k] = 0.25f * tanhf(__ldg(&kw[k]));
    int col = (c >= L_OUT) ? c - L_OUT : c;
    g_tile[c] = row_value(col, w);
}

__global__ void __launch_bounds__(TPB) tma_bcast_kernel(float* __restrict__ out) {
    __shared__ __align__(128) float4 tile[TILE_F4 + 1];

    // Fill smem tile from the precomputed pattern (hits L2 after first wave).
    const float4* src = reinterpret_cast<const float4*>(g_tile);
    for (int i = threadIdx.x; i < TILE_F4; i += TPB)
        tile[i] = src[i];
    __syncthreads();
    // Order generic-proxy smem writes before async-proxy (TMA) reads.
    asm volatile("fence.proxy.async.shared::cta;" ::: "memory");

    if (threadIdx.x == 0) {
        uint32_t saddr;
        asm("{ .reg .u64 t; cvta.to.shared.u64 t, %1; cvt.u32.u64 %0, t; }"
            : "=r"(saddr) : "l"(tile));
        char* base = reinterpret_cast<char*>(out)
                   + (size_t)blockIdx.x * G_PER_B * TILE_BYTES;
#pragma unroll
        for (int g = 0; g < G_PER_B; g++) {
            asm volatile(
                "cp.async.bulk.global.shared::cta.bulk_group [%0], [%1], %2;"
                :: "l"(base + (size_t)g * TILE_BYTES), "r"(saddr), "n"(TILE_BYTES)
                : "memory");
        }
        asm volatile("cp.async.bulk.commit_group;" ::: "memory");
        // Must complete before CTA exit releases the smem the TMA reads from.
        asm volatile("cp.async.bulk.wait_group 0;" ::: "memory");
    }
}

extern "C" void kernel_launch(void* const* d_in, const int* in_sizes, int n_in,
                              void* d_out, int out_size) {
    const float* kw = (const float*)d_in[1];   // kernel_weights [6]
    compute_tile_kernel<<<(TILE_FLOATS + 1023) / 1024, 1024>>>(kw);
    tma_bcast_kernel<<<NBLOCKS, TPB>>>((float*)d_out);
}

// round 4
// speedup vs baseline: 1.6611x; 1.6611x over previous
#include <cuda_runtime.h>

// out: [16384, 2046] f32 = tanh(row) broadcast over batch rows; row depends
// only on kernel_weights[6]. `values` is shape-only.
//
// Pattern period = 2 rows = 4092 floats = 1023 float4 (16B aligned). Each
// thread owns one float4 column slot, computes its 4 values once into
// registers, then streams write-through stores down the batch dimension.
// Write-through (st.global.wt) avoids the L2 write-allocate + dirty-writeback
// double pass that capped the evict-first version at ~24.9us.

#define BS       16384
#define L_OUT    2046
#define GROUPS   (BS / 2)              // 8192 two-row groups
#define F4_PER_G 1023                  // float4 per group
#define TPB      256
#define COL_BLK  4                     // 4*256 = 1024 threads cover 1023 slots
#define G_CHUNKS 512                   // batch-dim split over blockIdx.y
#define G_PER_B  (GROUPS / G_CHUNKS)   // 16 stores per thread

#define NEG_LOG_NORM 1.3836465597893728f   // -log(0.1*sqrt(2*pi))
#define INV_STD      10.0f

__device__ __forceinline__ float row_value(int c, const float* __restrict__ w) {
    const float means[6] = {0.0f, 0.2f, 0.4f, 0.6f, 0.8f, 1.0f};
    float pos = (float)c / (float)L_OUT;
    float acc = 0.0f;
#pragma unroll
    for (int k = 0; k < 6; k++) {
        float z = (pos - means[k]) * INV_STD;
        float pdf = expf(fmaf(-0.5f * z, z, NEG_LOG_NORM));
        acc = fmaf(w[k], pdf, acc);
    }
    return tanhf(acc);
}

__global__ void __launch_bounds__(TPB) bcast_wt_kernel(const float* __restrict__ kw,
                                                       float4* __restrict__ out) {
    int t = blockIdx.x * TPB + threadIdx.x;    // float4 slot within a group
    if (t >= F4_PER_G) return;

    float w[6];
#pragma unroll
    for (int k = 0; k < 6; k++) w[k] = 0.25f * tanhf(__ldg(&kw[k]));

    int e = 4 * t;
    int c0 = e;     if (c0 >= L_OUT) c0 -= L_OUT;
    int c1 = e + 1; if (c1 >= L_OUT) c1 -= L_OUT;
    int c2 = e + 2; if (c2 >= L_OUT) c2 -= L_OUT;
    int c3 = e + 3; if (c3 >= L_OUT) c3 -= L_OUT;

    float4 v;
    v.x = row_value(c0, w);
    v.y = row_value(c1, w);
    v.z = row_value(c2, w);
    v.w = row_value(c3, w);

    float4* p = out + (size_t)blockIdx.y * G_PER_B * F4_PER_G + t;
#pragma unroll 8
    for (int g = 0; g < G_PER_B; g++) {
        __stwt(p, v);          // write-through: one LTS pass, no writeback
        p += F4_PER_G;
    }
}

extern "C" void kernel_launch(void* const* d_in, const int* in_sizes, int n_in,
                              void* d_out, int out_size) {
    const float* kw = (const float*)d_in[1];   // kernel_weights [6]
    dim3 grid(COL_BLK, G_CHUNKS);              // 2048 blocks x 256 threads
    bcast_wt_kernel<<<grid, TPB>>>(kw, (float4*)d_out);
}